// round 15
// baseline (speedup 1.0000x reference)
#include <cuda_runtime.h>
#include <cuda_bf16.h>
#include <cuda_fp16.h>
#include <math.h>
#include <stdint.h>

#define B_   2
#define N_   2048
#define HID_ 768
#define H_   12
#define D_   64
#define W_   128
#define P_   257
#define PPAD 320
#define BH_  (B_*H_)      // 24
#define M_   (B_*N_)      // 4096

typedef __nv_bfloat16 bf16;

// ---------------- scratch ----------------
__device__ bf16  g_qh [BH_*N_*D_], g_ql [BH_*N_*D_];
__device__ bf16  g_kh [BH_*N_*D_], g_kl [BH_*N_*D_];
__device__ __half g_vf [BH_*N_*D_];          // V as single fp16
__device__ bf16  g_hsh[M_*HID_],   g_hsl[M_*HID_];
__device__ bf16  g_wqh[HID_*HID_], g_wql[HID_*HID_];
__device__ bf16  g_wkh[HID_*HID_], g_wkl[HID_*HID_];
__device__ bf16  g_wvh[HID_*HID_], g_wvl[HID_*HID_];
__device__ __half g_wof[HID_*HID_];          // Wo as single fp16
__device__ __half g_cthf[M_*HID_], g_ctlf[M_*HID_];   // ctx fp16 hi/lo
__device__ bf16  g_ptqh[H_*PPAD*D_], g_ptql[H_*PPAD*D_];
__device__ bf16  g_ptkh[H_*PPAD*D_], g_ptkl[H_*PPAD*D_];

// ---------------- helpers ----------------
__device__ __forceinline__ void mma_bf16(float* c, const uint32_t* a, const uint32_t* b) {
    asm volatile(
        "mma.sync.aligned.m16n8k16.row.col.f32.bf16.bf16.f32 "
        "{%0,%1,%2,%3},{%4,%5,%6,%7},{%8,%9},{%0,%1,%2,%3};\n"
        : "+f"(c[0]), "+f"(c[1]), "+f"(c[2]), "+f"(c[3])
        : "r"(a[0]), "r"(a[1]), "r"(a[2]), "r"(a[3]), "r"(b[0]), "r"(b[1]));
}
__device__ __forceinline__ void mma_f16(float* c, const uint32_t* a, const uint32_t* b) {
    asm volatile(
        "mma.sync.aligned.m16n8k16.row.col.f32.f16.f16.f32 "
        "{%0,%1,%2,%3},{%4,%5,%6,%7},{%8,%9},{%0,%1,%2,%3};\n"
        : "+f"(c[0]), "+f"(c[1]), "+f"(c[2]), "+f"(c[3])
        : "r"(a[0]), "r"(a[1]), "r"(a[2]), "r"(a[3]), "r"(b[0]), "r"(b[1]));
}
__device__ __forceinline__ void ldm4(uint32_t* r, uint32_t a) {
    asm volatile("ldmatrix.sync.aligned.m8n8.x4.shared.b16 {%0,%1,%2,%3},[%4];\n"
                 : "=r"(r[0]), "=r"(r[1]), "=r"(r[2]), "=r"(r[3]) : "r"(a));
}
__device__ __forceinline__ void ldm2t(uint32_t* r, uint32_t a) {
    asm volatile("ldmatrix.sync.aligned.m8n8.x2.trans.shared.b16 {%0,%1},[%2];\n"
                 : "=r"(r[0]), "=r"(r[1]) : "r"(a));
}
__device__ __forceinline__ void cpa16(uint32_t dst, const void* src) {
    asm volatile("cp.async.cg.shared.global [%0],[%1],16;\n" :: "r"(dst), "l"(src));
}
#define CP_COMMIT asm volatile("cp.async.commit_group;\n" ::: "memory")
#define CP_WAIT0  asm volatile("cp.async.wait_group 0;\n" ::: "memory")

__device__ __forceinline__ void split1(float v, bf16* hi, bf16* lo, size_t i) {
    bf16 h = __float2bfloat16_rn(v);
    hi[i] = h;
    lo[i] = __float2bfloat16_rn(v - __bfloat162float(h));
}

// ---------------- fused prep ----------------
#define SEG0 (M_*HID_)
#define SEGW (HID_*HID_)
#define SEGP (H_*PPAD*D_)
#define PREP_TOT (SEG0 + 4*SEGW + 2*SEGP)

__global__ void prep(const float* __restrict__ hs,
                     const float* __restrict__ Wq, const float* __restrict__ Wk,
                     const float* __restrict__ Wv, const float* __restrict__ Wo,
                     const float* __restrict__ pq, const float* __restrict__ pk)
{
    int i = blockIdx.x * 256 + threadIdx.x;
    if (i < SEG0) { split1(hs[i], g_hsh, g_hsl, i); return; }
    i -= SEG0;
    if (i < 4 * SEGW) {
        int t = i / SEGW, j = i - t * SEGW;
        if (t == 3) { g_wof[j] = __float2half_rn(Wo[j]); return; }
        const float* src = (t == 0) ? Wq : (t == 1) ? Wk : Wv;
        bf16* hi = (t == 0) ? g_wqh : (t == 1) ? g_wkh : g_wvh;
        bf16* lo = (t == 0) ? g_wql : (t == 1) ? g_wkl : g_wvl;
        split1(src[j], hi, lo, j);
        return;
    }
    i -= 4 * SEGW;
    if (i < 2 * SEGP) {
        int t = i / SEGP, j = i - t * SEGP;
        const float* pm = t ? pk : pq;
        bf16* hi = t ? g_ptkh : g_ptqh;
        bf16* lo = t ? g_ptkl : g_ptql;
        int d = j & 63;
        int rest = j >> 6;
        int p = rest % PPAD;
        int h = rest / PPAD;
        float v = (p < P_) ? pm[((size_t)h * D_ + d) * P_ + p] : 0.f;
        split1(v, hi, lo, j);
    }
}

// ---------------- split mma GEMM (128x64, 256 thr, occ2), PROD=3(bf16)/2(f16) ----------------
template<int PROD>
__global__ void __launch_bounds__(256, 2)
gemm_mma(const bf16* __restrict__ Ah, const bf16* __restrict__ Al, int lda,
         const bf16* Bh, const bf16* Bl, int ldb,
         int K, int nvalid, int mode,
         const float* __restrict__ bias,
         float* __restrict__ out, int ldo,
         bf16* sph, bf16* spl,
         const bf16* Bh1, const bf16* Bl1, const bf16* Bh2, const bf16* Bl2,
         bf16* sph1, bf16* spl1, bf16* sph2, bf16* spl2,
         float* pz, long long pztot)
{
    extern __shared__ char smraw[];
    uint32_t s_base = (uint32_t)__cvta_generic_to_shared(smraw);
    const int tid = threadIdx.x, warp = tid >> 5, l = tid & 31;
    const int m0 = blockIdx.y * 128;
    int n0;
    if (mode == 2) {
        int sel = blockIdx.x / 12;
        n0 = (blockIdx.x - sel * 12) * 64;
        if (sel == 1) { Bh = Bh1; Bl = Bl1; sph = sph1; spl = spl1; }
        else if (sel == 2) { Bh = Bh2; Bl = Bl2; sph = sph2; spl = spl2; }
    } else {
        n0 = blockIdx.x * 64;
    }

    auto load_stage = [&](int buf, int k0) {
        uint32_t sA  = s_base + buf * 49152;
        uint32_t sAl = sA + 16384;
        uint32_t sB  = sA + 32768;
        uint32_t sBl = sA + 40960;
        #pragma unroll
        for (int c = 0; c < 4; c++) {
            int idx = tid + c * 256;
            int m = idx >> 3, ku = idx & 7;
            uint32_t off = m * 128 + ((ku ^ (m & 7)) << 4);
            size_t src = (size_t)(m0 + m) * lda + k0 + ku * 8;
            cpa16(sA  + off, Ah + src);
            cpa16(sAl + off, Al + src);
        }
        #pragma unroll
        for (int c = 0; c < 2; c++) {
            int idx = tid + c * 256;
            int n = idx >> 3, ku = idx & 7;
            uint32_t off = n * 128 + ((ku ^ (n & 7)) << 4);
            size_t src = (size_t)(n0 + n) * ldb + k0 + ku * 8;
            cpa16(sB  + off, Bh + src);
            if (PROD == 3) cpa16(sBl + off, Bl + src);
        }
    };

    float acc[2][4][4];
    #pragma unroll
    for (int i = 0; i < 2; i++)
        #pragma unroll
        for (int nt = 0; nt < 4; nt++)
            #pragma unroll
            for (int u = 0; u < 4; u++) acc[i][nt][u] = 0.f;

    const int nst = K >> 6;
    load_stage(0, 0);
    CP_COMMIT;

    // zero-fill bookkeeping (spread across k-chunks)
    long long pzbase = 0, pzend = 0, pzpiece = 0;
    if (pz) {
        const long long chunk = 87384;
        pzbase = (long long)(blockIdx.y * gridDim.x + blockIdx.x) * chunk;
        pzend = pzbase + chunk;
        if (pzend > pztot) pzend = pztot;
        pzpiece = (chunk + nst - 1) / nst;
        pzpiece = (pzpiece + 3) & ~3LL;
    }

    const int wm = (warp >> 1) * 32, wn = (warp & 1) * 32;

    for (int ks = 0; ks < nst; ks++) {
        CP_WAIT0;
        __syncthreads();
        if (ks + 1 < nst) {
            load_stage((ks + 1) & 1, (ks + 1) << 6);
            CP_COMMIT;
        }

        // spread zero-fill: piece #ks
        if (pz) {
            long long s = pzbase + (long long)ks * pzpiece;
            long long e = s + pzpiece;
            if (e > pzend) e = pzend;
            float4 z4 = make_float4(0.f, 0.f, 0.f, 0.f);
            for (long long o = s + (long long)tid * 4; o < e; o += 1024)
                *(float4*)(pz + o) = z4;
        }

        uint32_t sA  = s_base + (ks & 1) * 49152;
        uint32_t sAl = sA + 16384;
        uint32_t sB  = sA + 32768;
        uint32_t sBl = sA + 40960;

        #pragma unroll
        for (int t = 0; t < 4; t++) {
            uint32_t fah[2][4], fal[2][4], fbh[8], fbl[8];
            #pragma unroll
            for (int i = 0; i < 2; i++) {
                int row = wm + 16 * i + (l & 7) + ((l >> 3) & 1) * 8;
                int ku  = 2 * t + (l >> 4);
                uint32_t off = row * 128 + ((ku ^ (row & 7)) << 4);
                ldm4(fah[i], sA  + off);
                ldm4(fal[i], sAl + off);
            }
            #pragma unroll
            for (int hh = 0; hh < 2; hh++) {
                int row = wn + 16 * hh + (l & 7) + ((l >> 4) & 1) * 8;
                int ku  = 2 * t + ((l >> 3) & 1);
                uint32_t off = row * 128 + ((ku ^ (row & 7)) << 4);
                ldm4(&fbh[hh * 4], sB  + off);
                if (PROD == 3) ldm4(&fbl[hh * 4], sBl + off);
            }
            #pragma unroll
            for (int i = 0; i < 2; i++)
                #pragma unroll
                for (int nt = 0; nt < 4; nt++) {
                    const uint32_t* bh2 = &fbh[(nt >> 1) * 4 + (nt & 1) * 2];
                    if (PROD == 3) {
                        const uint32_t* bl2 = &fbl[(nt >> 1) * 4 + (nt & 1) * 2];
                        mma_bf16(acc[i][nt], fah[i], bh2);
                        mma_bf16(acc[i][nt], fah[i], bl2);
                        mma_bf16(acc[i][nt], fal[i], bh2);
                    } else {
                        mma_f16(acc[i][nt], fah[i], bh2);
                        mma_f16(acc[i][nt], fal[i], bh2);
                    }
                }
        }
    }

    #pragma unroll
    for (int i = 0; i < 2; i++)
        #pragma unroll
        for (int nt = 0; nt < 4; nt++)
            #pragma unroll
            for (int cp = 0; cp < 2; cp++) {
                int r   = m0 + wm + 16 * i + (l >> 2) + cp * 8;
                int gn0 = n0 + wn + nt * 8 + (l & 3) * 2;
                float v0 = acc[i][nt][cp * 2 + 0];
                float v1 = acc[i][nt][cp * 2 + 1];
                if (mode == 0) {
                    if (gn0 < nvalid) {
                        float b0 = bias ? bias[gn0] : 0.f;
                        out[(size_t)r * ldo + gn0] = v0 + b0;
                    }
                    if (gn0 + 1 < nvalid) {
                        float b1 = bias ? bias[gn0 + 1] : 0.f;
                        out[(size_t)r * ldo + gn0 + 1] = v1 + b1;
                    }
                } else {
                    int b = r >> 11, nn = r & 2047;
                    #pragma unroll
                    for (int u = 0; u < 2; u++) {
                        int gn = gn0 + u;
                        float v = u ? v1 : v0;
                        int h = gn >> 6, d = gn & 63;
                        size_t idx = (((size_t)(b * H_ + h) * N_ + nn) << 6) + d;
                        if (spl == nullptr) {
                            ((__half*)sph)[idx] = __float2half_rn(v);   // V fp16 single
                        } else {
                            bf16 hv = __float2bfloat16_rn(v);
                            sph[idx] = hv;
                            spl[idx] = __float2bfloat16_rn(v - __bfloat162float(hv));
                        }
                    }
                }
            }
}

// ============== fully fused band attention (512 threads) ==============
#define OQH   0
#define OQL   4096
#define OKH   8192
#define OKL   49152
#define OPOSH 90112
#define OPOSL 131072
#define OPS   172032
#define OPH2  OPS
#define OPL2  (OPS + 20480)
#define SMEM_ATTN3 214016
#define KT2 320
#define KTV 288
#define PSW 328
#define AT_THREADS 512

__global__ void __launch_bounds__(AT_THREADS, 1)
attn_fused(const bf16* __restrict__ qh, const bf16* __restrict__ ql,
           const bf16* __restrict__ kh, const bf16* __restrict__ kl,
           const __half* __restrict__ vf,
           const bf16* __restrict__ ptkh, const bf16* __restrict__ ptkl,
           const bf16* __restrict__ ptqh, const bf16* __restrict__ ptql,
           float* __restrict__ proba, __half* __restrict__ cth, __half* __restrict__ ctl)
{
    const int bid = blockIdx.x;
    const int bh = bid >> 6, tile = bid & 63;
    const int h = bh % H_;
    const int i0 = tile * 32;
    const int jlo = max(0, i0 - W_);
    const int jhi = min(N_, i0 + 32 + W_);
    const int nk = jhi - jlo;          // <= 288
    const int S0 = i0 - jlo + W_;

    extern __shared__ char sm[];
    const uint32_t sb = (uint32_t)__cvta_generic_to_shared(sm);
    const int tid = threadIdx.x, warp = tid >> 5, l = tid & 31;
    const size_t gbase = (size_t)bh * N_ * D_;
    const size_t pbase = (size_t)h * PPAD * D_;
    float* Ps = (float*)(sm + OPS);

    {
        int idx = tid;
        int m = idx & 255;
        int r = m >> 3, ku = m & 7;
        uint32_t off = r * 128 + ((ku ^ (r & 7)) << 4);
        size_t s = gbase + (size_t)(i0 + r) * 64 + ku * 8;
        if (idx < 256) cpa16(sb + OQH + off, qh + s);
        else           cpa16(sb + OQL + off, ql + s);
    }
    for (int idx = tid; idx < nk * 8; idx += AT_THREADS) {
        int r = idx >> 3, ku = idx & 7;
        uint32_t off = r * 128 + ((ku ^ (r & 7)) << 4);
        size_t s = gbase + (size_t)(jlo + r) * 64 + ku * 8;
        cpa16(sb + OKH + off, kh + s);
        cpa16(sb + OKL + off, kl + s);
    }
    for (int idx = tid; idx < KT2 * 8; idx += AT_THREADS) {
        int r = idx >> 3, ku = idx & 7;
        uint32_t off = r * 128 + ((ku ^ (r & 7)) << 4);
        size_t s = pbase + (size_t)r * 64 + ku * 8;
        cpa16(sb + OPOSH + off, ptkh + s);
        cpa16(sb + OPOSL + off, ptkl + s);
    }
    CP_COMMIT;
    CP_WAIT0;
    __syncthreads();

    // fused phases A+B (bf16 3-product); K+PK fragments fused into single ldm4
    {
        const int mh    = warp >> 3;
        const int m0w   = mh << 4;
        const int nbase = (warp & 7) << 3;
        float c[5][4], dd[5][4];
        #pragma unroll
        for (int t5 = 0; t5 < 5; t5++)
            #pragma unroll
            for (int u = 0; u < 4; u++) { c[t5][u] = 0.f; dd[t5][u] = 0.f; }

        const uint32_t bhi = (l < 16) ? (sb + OKH) : (sb + OPOSH);
        const uint32_t blo = (l < 16) ? (sb + OKL) : (sb + OPOSL);

        #pragma unroll
        for (int ks = 0; ks < 4; ks++) {
            uint32_t fah[4], fal[4];
            int arow = m0w + (l & 7) + ((l >> 3) & 1) * 8;
            int aku  = 2 * ks + (l >> 4);
            uint32_t aoff = arow * 128 + ((aku ^ (arow & 7)) << 4);
            ldm4(fah, sb + OQH + aoff);
            ldm4(fal, sb + OQL + aoff);
            #pragma unroll
            for (int t5 = 0; t5 < 5; t5++) {
                int brow = nbase + t5 * 64 + (l & 7);
                int bku  = 2 * ks + ((l >> 3) & 1);
                uint32_t boff = brow * 128 + ((bku ^ (brow & 7)) << 4);
                uint32_t fb[4], fbl2[4];
                ldm4(fb,   bhi + boff);
                ldm4(fbl2, blo + boff);
                mma_bf16(c[t5],  fah, fb);
                mma_bf16(c[t5],  fah, fbl2);
                mma_bf16(c[t5],  fal, fb);
                mma_bf16(dd[t5], fah, fb + 2);
                mma_bf16(dd[t5], fah, fbl2 + 2);
                mma_bf16(dd[t5], fal, fb + 2);
            }
        }
        #pragma unroll
        for (int t5 = 0; t5 < 5; t5++) {
            int col = nbase + t5 * 64 + (l & 3) * 2;
            int row = m0w + (l >> 2);
            *(float2*)&Ps[row * PSW + col]       = make_float2(c[t5][0], c[t5][1]);
            *(float2*)&Ps[(row + 8) * PSW + col] = make_float2(c[t5][2], c[t5][3]);
        }
        __syncthreads();
        const int sh = S0 - 256;
        #pragma unroll
        for (int t5 = 0; t5 < 5; t5++)
            #pragma unroll
            for (int reg = 0; reg < 4; reg++) {
                int qi  = m0w + (l >> 2) + ((reg >> 1) << 3);
                int rel = nbase + t5 * 64 + ((l & 3) << 1) + (reg & 1);
                int jj  = qi + rel + sh;
                if (jj >= 0 && jj < nk)
                    Ps[qi * PSW + jj] += dd[t5][reg];
            }
    }
    __syncthreads();

    // load PQ over PK region
    for (int idx = tid; idx < KT2 * 8; idx += AT_THREADS) {
        int r = idx >> 3, ku = idx & 7;
        uint32_t off = r * 128 + ((ku ^ (r & 7)) << 4);
        size_t s = pbase + (size_t)r * 64 + ku * 8;
        cpa16(sb + OPOSH + off, ptqh + s);
        cpa16(sb + OPOSL + off, ptql + s);
    }
    CP_COMMIT;
    CP_WAIT0;
    __syncthreads();

    // phase C (bf16 3-product)
    for (int g = warp; g < 20; g += 16) {
        if (16 * g >= nk) continue;
        const int cb = S0 - 16 * g - 15;
        float c[6][4];
        #pragma unroll
        for (int nt = 0; nt < 6; nt++)
            #pragma unroll
            for (int u = 0; u < 4; u++) c[nt][u] = 0.f;
        #pragma unroll
        for (int kc = 0; kc < 4; kc++) {
            uint32_t fah[4], fal[4];
            int arow = 16 * g + (l & 7) + ((l >> 3) & 1) * 8;
            int aku  = 2 * kc + (l >> 4);
            uint32_t aoff = arow * 128 + ((aku ^ (arow & 7)) << 4);
            ldm4(fah, sb + OKH + aoff);
            ldm4(fal, sb + OKL + aoff);
            #pragma unroll
            for (int nt3 = 0; nt3 < 3; nt3++) {
                int brel = cb + nt3 * 16 + (l & 7) + ((l >> 4) & 1) * 8;
                int brow = min(max(brel, 0), KT2 - 1);
                int bku  = 2 * kc + ((l >> 3) & 1);
                uint32_t boff = brow * 128 + ((bku ^ (brow & 7)) << 4);
                uint32_t fbh[4], fbl[4];
                ldm4(fbh, sb + OPOSH + boff);
                ldm4(fbl, sb + OPOSL + boff);
                #pragma unroll
                for (int hh = 0; hh < 2; hh++) {
                    mma_bf16(c[nt3 * 2 + hh], fah, fbh + hh * 2);
                    mma_bf16(c[nt3 * 2 + hh], fah, fbl + hh * 2);
                    mma_bf16(c[nt3 * 2 + hh], fal, fbh + hh * 2);
                }
            }
        }
        #pragma unroll
        for (int nt = 0; nt < 6; nt++)
            #pragma unroll
            for (int reg = 0; reg < 4; reg++) {
                int jj  = 16 * g + (l >> 2) + ((reg >> 1) << 3);
                int rel = cb + nt * 8 + ((l & 3) << 1) + (reg & 1);
                int qi  = rel + jj - S0;
                if (rel >= 0 && qi >= 0 && qi < 32 && jj < nk)
                    Ps[qi * PSW + jj] += c[nt][reg];
            }
    }
    __syncthreads();

    // load V (single fp16, 288 rows) over POS region; zero pads to 288
    for (int idx = tid; idx < nk * 8; idx += AT_THREADS) {
        int r = idx >> 3, ku = idx & 7;
        uint32_t off = r * 128 + ((ku ^ (r & 7)) << 4);
        size_t s = gbase + (size_t)(jlo + r) * 64 + ku * 8;
        cpa16(sb + OPOSH + off, vf + s);
    }
    CP_COMMIT;
    {
        uint4 z = {0, 0, 0, 0};
        for (int idx = tid; idx < (KTV - nk) * 8; idx += AT_THREADS) {
            int r = nk + (idx >> 3), ku = idx & 7;
            uint32_t off = r * 128 + ((ku ^ (r & 7)) << 4);
            *(uint4*)(sm + OPOSH + off) = z;
        }
    }

    // softmax
    const int qi = tid >> 4, lane16 = tid & 15;
    const int i = i0 + qi;
    float sreg[20];
    {
        float lmax = -INFINITY;
        #pragma unroll
        for (int t = 0; t < 20; t++) {
            int jj = lane16 + (t << 4);
            int rel = (jlo + jj) - i + W_;
            float s = -INFINITY;
            if (jj < nk && rel >= 0 && rel <= 2 * W_)
                s = Ps[qi * PSW + jj];
            sreg[t] = s;
            lmax = fmaxf(lmax, s);
        }
        #pragma unroll
        for (int off = 8; off; off >>= 1)
            lmax = fmaxf(lmax, __shfl_xor_sync(0xffffffffu, lmax, off));
        float lsum = 0.f;
        #pragma unroll
        for (int t = 0; t < 20; t++) {
            float e = __expf(sreg[t] - lmax);
            sreg[t] = e;
            lsum += e;
        }
        #pragma unroll
        for (int off = 8; off; off >>= 1)
            lsum += __shfl_xor_sync(0xffffffffu, lsum, off);
        const float rinv = 1.f / lsum;
        #pragma unroll
        for (int t = 0; t < 20; t++) sreg[t] *= rinv;
    }
    __syncthreads();

    // probs as fp16 hi/lo
    #pragma unroll
    for (int t = 0; t < 20; t++) {
        int jj = lane16 + (t << 4);
        float p = sreg[t];
        __half ph = __float2half_rn(p);
        __half pl = __float2half_rn(p - __half2float(ph));
        int ku = jj >> 3;
        uint32_t boff = qi * 640 + ((((ku & 7) ^ (qi & 7)) | (ku & ~7)) << 4) + ((jj & 7) << 1);
        *(__half*)(sm + OPH2 + boff) = ph;
        *(__half*)(sm + OPL2 + boff) = pl;
    }
    CP_WAIT0;
    __syncthreads();

    // final: warps 0-7 ctx MMA (f16 2-product, 18 K-slices = 288 rows), warps 8-15 proba
    if (warp < 8) {
        const int n0w = warp << 3;
        float c[2][4];
        #pragma unroll
        for (int mh = 0; mh < 2; mh++)
            #pragma unroll
            for (int u = 0; u < 4; u++) c[mh][u] = 0.f;
        #pragma unroll
        for (int ks = 0; ks < 18; ks++) {
            uint32_t fvh[2];
            {
                int jr  = ks * 16 + (l & 15);
                int kuv = warp;
                uint32_t off = jr * 128 + ((kuv ^ (jr & 7)) << 4);
                ldm2t(fvh, sb + OPOSH + off);
            }
            #pragma unroll
            for (int mh = 0; mh < 2; mh++) {
                uint32_t fah[4], fal[4];
                int row = (mh << 4) + (l & 7) + ((l >> 3) & 1) * 8;
                int ku  = 2 * ks + (l >> 4);
                uint32_t off = row * 640 + ((((ku & 7) ^ (row & 7)) | (ku & ~7)) << 4);
                ldm4(fah, sb + OPH2 + off);
                ldm4(fal, sb + OPL2 + off);
                mma_f16(c[mh], fah, fvh);
                mma_f16(c[mh], fal, fvh);
            }
        }
        int b = bh / H_, hd = bh - b * H_;
        #pragma unroll
        for (int mh = 0; mh < 2; mh++) {
            int d  = n0w + (l & 3) * 2;
            int r0 = i0 + (mh << 4) + (l >> 2);
            size_t p0 = ((size_t)(b * N_ + r0)) * HID_ + hd * 64 + d;
            #pragma unroll
            for (int cp = 0; cp < 2; cp++) {
                size_t pp = p0 + (size_t)cp * 8 * HID_;
                float v0 = c[mh][cp * 2 + 0], v1 = c[mh][cp * 2 + 1];
                __half h0 = __float2half_rn(v0), h1 = __float2half_rn(v1);
                __half l0 = __float2half_rn(v0 - __half2float(h0));
                __half l1 = __float2half_rn(v1 - __half2float(h1));
                *(__half2*)(cth + pp) = __halves2half2(h0, h1);
                *(__half2*)(ctl + pp) = __halves2half2(l0, l1);
            }
        }
    } else if (proba) {
        const int w4 = warp - 8;
        const int nf4 = nk >> 2;
        for (int qq = w4 * 4; qq < w4 * 4 + 4; qq++) {
            int ii = i0 + qq;
            float* prow = proba + ((size_t)bh * N_ + ii) * N_ + jlo;
            for (int f4 = l; f4 < nf4; f4 += 32) {
                int j4 = f4 << 2;
                float4 v;
                #pragma unroll
                for (int u = 0; u < 4; u++) {
                    int jj = j4 + u;
                    int ku = jj >> 3;
                    uint32_t boff = qq * 640 + ((((ku & 7) ^ (qq & 7)) | (ku & ~7)) << 4) + ((jj & 7) << 1);
                    ((float*)&v)[u] = __half2float(*(__half*)(sm + OPH2 + boff)) +
                                      __half2float(*(__half*)(sm + OPL2 + boff));
                }
                *(float4*)(prow + j4) = v;
            }
        }
    }
}

// ================================ launch ================================
extern "C" void kernel_launch(void* const* d_in, const int* in_sizes, int n_in,
                              void* d_out, int out_size) {
    const float* hs = (const float*)d_in[0];
    const float* Wq = (const float*)d_in[2];
    const float* Wk = (const float*)d_in[3];
    const float* Wv = (const float*)d_in[4];
    const float* pq = (const float*)d_in[5];
    const float* pk = (const float*)d_in[6];
    const float* Wo = (const float*)d_in[7];
    const float* bo = (const float*)d_in[8];

    const long long OUT_E   = (long long)M_ * HID_;
    const long long PROBA_E = (long long)BH_ * N_ * N_;
    float* out_ptr = nullptr; float* proba_ptr = nullptr;
    if ((long long)out_size == OUT_E + PROBA_E) {
        out_ptr = (float*)d_out; proba_ptr = (float*)d_out + OUT_E;
    } else if ((long long)out_size == PROBA_E) {
        proba_ptr = (float*)d_out;
    } else {
        out_ptr = (float*)d_out;
    }

    bf16 *pQh, *pQl, *pKh, *pKl, *pHh, *pHl;
    bf16 *pWqh, *pWql, *pWkh, *pWkl, *pWvh, *pWvl;
    bf16 *pPQh, *pPQl, *pPKh, *pPKl;
    __half *pVf, *pWof, *pCh, *pCl;
    cudaGetSymbolAddress((void**)&pQh, g_qh);   cudaGetSymbolAddress((void**)&pQl, g_ql);
    cudaGetSymbolAddress((void**)&pKh, g_kh);   cudaGetSymbolAddress((void**)&pKl, g_kl);
    cudaGetSymbolAddress((void**)&pVf, g_vf);
    cudaGetSymbolAddress((void**)&pHh, g_hsh);  cudaGetSymbolAddress((void**)&pHl, g_hsl);
    cudaGetSymbolAddress((void**)&pCh, g_cthf); cudaGetSymbolAddress((void**)&pCl, g_ctlf);
    cudaGetSymbolAddress((void**)&pWqh, g_wqh); cudaGetSymbolAddress((void**)&pWql, g_wql);
    cudaGetSymbolAddress((void**)&pWkh, g_wkh); cudaGetSymbolAddress((void**)&pWkl, g_wkl);
    cudaGetSymbolAddress((void**)&pWvh, g_wvh); cudaGetSymbolAddress((void**)&pWvl, g_wvl);
    cudaGetSymbolAddress((void**)&pWof, g_wof);
    cudaGetSymbolAddress((void**)&pPQh, g_ptqh); cudaGetSymbolAddress((void**)&pPQl, g_ptql);
    cudaGetSymbolAddress((void**)&pPKh, g_ptkh); cudaGetSymbolAddress((void**)&pPKl, g_ptkl);

    // 0: fused prep
    prep<<<(PREP_TOT + 255) / 256, 256>>>(hs, Wq, Wk, Wv, Wo, pq, pk);

    cudaFuncSetAttribute(gemm_mma<3>, cudaFuncAttributeMaxDynamicSharedMemorySize, 98304);
    cudaFuncSetAttribute(gemm_mma<2>, cudaFuncAttributeMaxDynamicSharedMemorySize, 98304);

    // 1: fused QKV projection (+ spread proba zero-fill); V written as fp16 single
    dim3 gQKV(36, M_ / 128);
    gemm_mma<3><<<gQKV, 256, 98304>>>(pHh, pHl, HID_, pWqh, pWql, HID_, HID_, HID_,
                                      2, nullptr, nullptr, 0, pQh, pQl,
                                      pWkh, pWkl, pWvh, pWvl, pKh, pKl,
                                      (bf16*)pVf, nullptr,
                                      proba_ptr, PROBA_E);

    // 2: fully fused band attention
    cudaFuncSetAttribute(attn_fused, cudaFuncAttributeMaxDynamicSharedMemorySize, SMEM_ATTN3);
    attn_fused<<<BH_ * (N_ / 32), AT_THREADS, SMEM_ATTN3>>>(pQh, pQl, pKh, pKl, pVf,
                                                            pPKh, pPKl, pPQh, pPQl,
                                                            proba_ptr, pCh, pCl);

    // 3: output projection (f16 2-product)
    if (out_ptr) {
        dim3 gO(HID_ / 64, M_ / 128);
        gemm_mma<2><<<gO, 256, 98304>>>((bf16*)pCh, (bf16*)pCl, HID_,
                                        (bf16*)pWof, nullptr, HID_, HID_, HID_,
                                        0, bo, out_ptr, HID_, nullptr, nullptr,
                                        nullptr, nullptr, nullptr, nullptr,
                                        nullptr, nullptr, nullptr, nullptr,
                                        nullptr, 0);
    }
}

// round 16
// speedup vs baseline: 1.0056x; 1.0056x over previous
#include <cuda_runtime.h>
#include <cuda_bf16.h>
#include <cuda_fp16.h>
#include <math.h>
#include <stdint.h>

#define B_   2
#define N_   2048
#define HID_ 768
#define H_   12
#define D_   64
#define W_   128
#define P_   257
#define PPAD 320
#define BH_  (B_*H_)      // 24
#define M_   (B_*N_)      // 4096

typedef __nv_bfloat16 bf16;

// ---------------- scratch ----------------
__device__ bf16  g_qh [BH_*N_*D_], g_ql [BH_*N_*D_];
__device__ bf16  g_kh [BH_*N_*D_], g_kl [BH_*N_*D_];
__device__ __half g_vf [BH_*N_*D_];          // V as single fp16
__device__ bf16  g_hsh[M_*HID_],   g_hsl[M_*HID_];
__device__ bf16  g_wqh[HID_*HID_], g_wql[HID_*HID_];
__device__ bf16  g_wkh[HID_*HID_], g_wkl[HID_*HID_];
__device__ bf16  g_wvh[HID_*HID_], g_wvl[HID_*HID_];
__device__ __half g_wof[HID_*HID_];          // Wo as single fp16
__device__ __half g_cthf[M_*HID_], g_ctlf[M_*HID_];   // ctx fp16 hi/lo
__device__ bf16  g_ptqh[H_*PPAD*D_], g_ptql[H_*PPAD*D_];
__device__ bf16  g_ptkh[H_*PPAD*D_], g_ptkl[H_*PPAD*D_];

// ---------------- helpers ----------------
__device__ __forceinline__ void mma_bf16(float* c, const uint32_t* a, const uint32_t* b) {
    asm volatile(
        "mma.sync.aligned.m16n8k16.row.col.f32.bf16.bf16.f32 "
        "{%0,%1,%2,%3},{%4,%5,%6,%7},{%8,%9},{%0,%1,%2,%3};\n"
        : "+f"(c[0]), "+f"(c[1]), "+f"(c[2]), "+f"(c[3])
        : "r"(a[0]), "r"(a[1]), "r"(a[2]), "r"(a[3]), "r"(b[0]), "r"(b[1]));
}
__device__ __forceinline__ void mma_f16(float* c, const uint32_t* a, const uint32_t* b) {
    asm volatile(
        "mma.sync.aligned.m16n8k16.row.col.f32.f16.f16.f32 "
        "{%0,%1,%2,%3},{%4,%5,%6,%7},{%8,%9},{%0,%1,%2,%3};\n"
        : "+f"(c[0]), "+f"(c[1]), "+f"(c[2]), "+f"(c[3])
        : "r"(a[0]), "r"(a[1]), "r"(a[2]), "r"(a[3]), "r"(b[0]), "r"(b[1]));
}
__device__ __forceinline__ void ldm4(uint32_t* r, uint32_t a) {
    asm volatile("ldmatrix.sync.aligned.m8n8.x4.shared.b16 {%0,%1,%2,%3},[%4];\n"
                 : "=r"(r[0]), "=r"(r[1]), "=r"(r[2]), "=r"(r[3]) : "r"(a));
}
__device__ __forceinline__ void ldm2t(uint32_t* r, uint32_t a) {
    asm volatile("ldmatrix.sync.aligned.m8n8.x2.trans.shared.b16 {%0,%1},[%2];\n"
                 : "=r"(r[0]), "=r"(r[1]) : "r"(a));
}
__device__ __forceinline__ void cpa16(uint32_t dst, const void* src) {
    asm volatile("cp.async.cg.shared.global [%0],[%1],16;\n" :: "r"(dst), "l"(src));
}
#define CP_COMMIT asm volatile("cp.async.commit_group;\n" ::: "memory")
#define CP_WAIT0  asm volatile("cp.async.wait_group 0;\n" ::: "memory")

__device__ __forceinline__ void split1(float v, bf16* hi, bf16* lo, size_t i) {
    bf16 h = __float2bfloat16_rn(v);
    hi[i] = h;
    lo[i] = __float2bfloat16_rn(v - __bfloat162float(h));
}

// ---------------- fused prep ----------------
#define SEG0 (M_*HID_)
#define SEGW (HID_*HID_)
#define SEGP (H_*PPAD*D_)
#define PREP_TOT (SEG0 + 4*SEGW + 2*SEGP)

__global__ void prep(const float* __restrict__ hs,
                     const float* __restrict__ Wq, const float* __restrict__ Wk,
                     const float* __restrict__ Wv, const float* __restrict__ Wo,
                     const float* __restrict__ pq, const float* __restrict__ pk)
{
    int i = blockIdx.x * 256 + threadIdx.x;
    if (i < SEG0) { split1(hs[i], g_hsh, g_hsl, i); return; }
    i -= SEG0;
    if (i < 4 * SEGW) {
        int t = i / SEGW, j = i - t * SEGW;
        if (t == 3) { g_wof[j] = __float2half_rn(Wo[j]); return; }
        const float* src = (t == 0) ? Wq : (t == 1) ? Wk : Wv;
        bf16* hi = (t == 0) ? g_wqh : (t == 1) ? g_wkh : g_wvh;
        bf16* lo = (t == 0) ? g_wql : (t == 1) ? g_wkl : g_wvl;
        split1(src[j], hi, lo, j);
        return;
    }
    i -= 4 * SEGW;
    if (i < 2 * SEGP) {
        int t = i / SEGP, j = i - t * SEGP;
        const float* pm = t ? pk : pq;
        bf16* hi = t ? g_ptkh : g_ptqh;
        bf16* lo = t ? g_ptkl : g_ptql;
        int d = j & 63;
        int rest = j >> 6;
        int p = rest % PPAD;
        int h = rest / PPAD;
        float v = (p < P_) ? pm[((size_t)h * D_ + d) * P_ + p] : 0.f;
        split1(v, hi, lo, j);
    }
}

// ---------------- split mma GEMM (128x64, 256 thr, occ2), PROD=3(bf16)/2(f16) ----------------
template<int PROD>
__global__ void __launch_bounds__(256, 2)
gemm_mma(const bf16* __restrict__ Ah, const bf16* __restrict__ Al, int lda,
         const bf16* Bh, const bf16* Bl, int ldb,
         int K, int nvalid, int mode,
         const float* __restrict__ bias,
         float* __restrict__ out, int ldo,
         bf16* sph, bf16* spl,
         const bf16* Bh1, const bf16* Bl1, const bf16* Bh2, const bf16* Bl2,
         bf16* sph1, bf16* spl1, bf16* sph2, bf16* spl2,
         float* pz, long long pztot)
{
    extern __shared__ char smraw[];
    uint32_t s_base = (uint32_t)__cvta_generic_to_shared(smraw);
    const int tid = threadIdx.x, warp = tid >> 5, l = tid & 31;
    const int m0 = blockIdx.y * 128;
    int n0;
    if (mode == 2) {
        int sel = blockIdx.x / 12;
        n0 = (blockIdx.x - sel * 12) * 64;
        if (sel == 1) { Bh = Bh1; Bl = Bl1; sph = sph1; spl = spl1; }
        else if (sel == 2) { Bh = Bh2; Bl = Bl2; sph = sph2; spl = spl2; }
    } else {
        n0 = blockIdx.x * 64;
    }

    auto load_stage = [&](int buf, int k0) {
        uint32_t sA  = s_base + buf * 49152;
        uint32_t sAl = sA + 16384;
        uint32_t sB  = sA + 32768;
        uint32_t sBl = sA + 40960;
        #pragma unroll
        for (int c = 0; c < 4; c++) {
            int idx = tid + c * 256;
            int m = idx >> 3, ku = idx & 7;
            uint32_t off = m * 128 + ((ku ^ (m & 7)) << 4);
            size_t src = (size_t)(m0 + m) * lda + k0 + ku * 8;
            cpa16(sA  + off, Ah + src);
            cpa16(sAl + off, Al + src);
        }
        #pragma unroll
        for (int c = 0; c < 2; c++) {
            int idx = tid + c * 256;
            int n = idx >> 3, ku = idx & 7;
            uint32_t off = n * 128 + ((ku ^ (n & 7)) << 4);
            size_t src = (size_t)(n0 + n) * ldb + k0 + ku * 8;
            cpa16(sB  + off, Bh + src);
            if (PROD == 3) cpa16(sBl + off, Bl + src);
        }
    };

    float acc[2][4][4];
    #pragma unroll
    for (int i = 0; i < 2; i++)
        #pragma unroll
        for (int nt = 0; nt < 4; nt++)
            #pragma unroll
            for (int u = 0; u < 4; u++) acc[i][nt][u] = 0.f;

    const int nst = K >> 6;
    load_stage(0, 0);
    CP_COMMIT;

    if (pz) {
        const long long chunk = 87384;
        long long base = (long long)(blockIdx.y * gridDim.x + blockIdx.x) * chunk;
        long long end = base + chunk;
        if (end > pztot) end = pztot;
        float4 z4 = make_float4(0.f, 0.f, 0.f, 0.f);
        for (long long o = base + (long long)tid * 4; o < end; o += 1024)
            *(float4*)(pz + o) = z4;
    }

    const int wm = (warp >> 1) * 32, wn = (warp & 1) * 32;

    for (int ks = 0; ks < nst; ks++) {
        CP_WAIT0;
        __syncthreads();
        if (ks + 1 < nst) {
            load_stage((ks + 1) & 1, (ks + 1) << 6);
            CP_COMMIT;
        }

        uint32_t sA  = s_base + (ks & 1) * 49152;
        uint32_t sAl = sA + 16384;
        uint32_t sB  = sA + 32768;
        uint32_t sBl = sA + 40960;

        #pragma unroll
        for (int t = 0; t < 4; t++) {
            uint32_t fah[2][4], fal[2][4], fbh[8], fbl[8];
            #pragma unroll
            for (int i = 0; i < 2; i++) {
                int row = wm + 16 * i + (l & 7) + ((l >> 3) & 1) * 8;
                int ku  = 2 * t + (l >> 4);
                uint32_t off = row * 128 + ((ku ^ (row & 7)) << 4);
                ldm4(fah[i], sA  + off);
                ldm4(fal[i], sAl + off);
            }
            #pragma unroll
            for (int hh = 0; hh < 2; hh++) {
                int row = wn + 16 * hh + (l & 7) + ((l >> 4) & 1) * 8;
                int ku  = 2 * t + ((l >> 3) & 1);
                uint32_t off = row * 128 + ((ku ^ (row & 7)) << 4);
                ldm4(&fbh[hh * 4], sB  + off);
                if (PROD == 3) ldm4(&fbl[hh * 4], sBl + off);
            }
            #pragma unroll
            for (int i = 0; i < 2; i++)
                #pragma unroll
                for (int nt = 0; nt < 4; nt++) {
                    const uint32_t* bh2 = &fbh[(nt >> 1) * 4 + (nt & 1) * 2];
                    if (PROD == 3) {
                        const uint32_t* bl2 = &fbl[(nt >> 1) * 4 + (nt & 1) * 2];
                        mma_bf16(acc[i][nt], fah[i], bh2);
                        mma_bf16(acc[i][nt], fah[i], bl2);
                        mma_bf16(acc[i][nt], fal[i], bh2);
                    } else {
                        mma_f16(acc[i][nt], fah[i], bh2);
                        mma_f16(acc[i][nt], fal[i], bh2);
                    }
                }
        }
    }

    #pragma unroll
    for (int i = 0; i < 2; i++)
        #pragma unroll
        for (int nt = 0; nt < 4; nt++)
            #pragma unroll
            for (int cp = 0; cp < 2; cp++) {
                int r   = m0 + wm + 16 * i + (l >> 2) + cp * 8;
                int gn0 = n0 + wn + nt * 8 + (l & 3) * 2;
                float v0 = acc[i][nt][cp * 2 + 0];
                float v1 = acc[i][nt][cp * 2 + 1];
                if (mode == 0) {
                    if (gn0 < nvalid) {
                        float b0 = bias ? bias[gn0] : 0.f;
                        out[(size_t)r * ldo + gn0] = v0 + b0;
                    }
                    if (gn0 + 1 < nvalid) {
                        float b1 = bias ? bias[gn0 + 1] : 0.f;
                        out[(size_t)r * ldo + gn0 + 1] = v1 + b1;
                    }
                } else {
                    int b = r >> 11, nn = r & 2047;
                    #pragma unroll
                    for (int u = 0; u < 2; u++) {
                        int gn = gn0 + u;
                        float v = u ? v1 : v0;
                        int h = gn >> 6, d = gn & 63;
                        size_t idx = (((size_t)(b * H_ + h) * N_ + nn) << 6) + d;
                        if (spl == nullptr) {
                            ((__half*)sph)[idx] = __float2half_rn(v);   // V fp16 single
                        } else {
                            bf16 hv = __float2bfloat16_rn(v);
                            sph[idx] = hv;
                            spl[idx] = __float2bfloat16_rn(v - __bfloat162float(hv));
                        }
                    }
                }
            }
}

// ============== fully fused band attention (512 threads) ==============
#define OQH   0
#define OQL   4096
#define OKH   8192
#define OKL   49152
#define OPOSH 90112
#define OPOSL 131072
#define OPS   172032
#define OPH2  OPS
#define OPL2  (OPS + 20480)
#define SMEM_ATTN3 214016
#define KT2 320
#define KTV 288
#define PSW 328
#define AT_THREADS 512

__global__ void __launch_bounds__(AT_THREADS, 1)
attn_fused(const bf16* __restrict__ qh, const bf16* __restrict__ ql,
           const bf16* __restrict__ kh, const bf16* __restrict__ kl,
           const __half* __restrict__ vf,
           const bf16* __restrict__ ptkh, const bf16* __restrict__ ptkl,
           const bf16* __restrict__ ptqh, const bf16* __restrict__ ptql,
           float* __restrict__ proba, __half* __restrict__ cth, __half* __restrict__ ctl)
{
    const int bid = blockIdx.x;
    const int bh = bid >> 6, tile = bid & 63;
    const int h = bh % H_;
    const int i0 = tile * 32;
    const int jlo = max(0, i0 - W_);
    const int jhi = min(N_, i0 + 32 + W_);
    const int nk = jhi - jlo;          // <= 288
    const int S0 = i0 - jlo + W_;

    extern __shared__ char sm[];
    const uint32_t sb = (uint32_t)__cvta_generic_to_shared(sm);
    const int tid = threadIdx.x, warp = tid >> 5, l = tid & 31;
    const size_t gbase = (size_t)bh * N_ * D_;
    const size_t pbase = (size_t)h * PPAD * D_;
    float* Ps = (float*)(sm + OPS);

    {
        int idx = tid;
        int m = idx & 255;
        int r = m >> 3, ku = m & 7;
        uint32_t off = r * 128 + ((ku ^ (r & 7)) << 4);
        size_t s = gbase + (size_t)(i0 + r) * 64 + ku * 8;
        if (idx < 256) cpa16(sb + OQH + off, qh + s);
        else           cpa16(sb + OQL + off, ql + s);
    }
    for (int idx = tid; idx < nk * 8; idx += AT_THREADS) {
        int r = idx >> 3, ku = idx & 7;
        uint32_t off = r * 128 + ((ku ^ (r & 7)) << 4);
        size_t s = gbase + (size_t)(jlo + r) * 64 + ku * 8;
        cpa16(sb + OKH + off, kh + s);
        cpa16(sb + OKL + off, kl + s);
    }
    for (int idx = tid; idx < KT2 * 8; idx += AT_THREADS) {
        int r = idx >> 3, ku = idx & 7;
        uint32_t off = r * 128 + ((ku ^ (r & 7)) << 4);
        size_t s = pbase + (size_t)r * 64 + ku * 8;
        cpa16(sb + OPOSH + off, ptkh + s);
        cpa16(sb + OPOSL + off, ptkl + s);
    }
    CP_COMMIT;
    CP_WAIT0;
    __syncthreads();

    // fused phases A+B (bf16 3-product); K+PK fragments fused into single ldm4
    {
        const int mh    = warp >> 3;
        const int m0w   = mh << 4;
        const int nbase = (warp & 7) << 3;
        float c[5][4], dd[5][4];
        #pragma unroll
        for (int t5 = 0; t5 < 5; t5++)
            #pragma unroll
            for (int u = 0; u < 4; u++) { c[t5][u] = 0.f; dd[t5][u] = 0.f; }

        const uint32_t bhi = (l < 16) ? (sb + OKH) : (sb + OPOSH);
        const uint32_t blo = (l < 16) ? (sb + OKL) : (sb + OPOSL);

        #pragma unroll
        for (int ks = 0; ks < 4; ks++) {
            uint32_t fah[4], fal[4];
            int arow = m0w + (l & 7) + ((l >> 3) & 1) * 8;
            int aku  = 2 * ks + (l >> 4);
            uint32_t aoff = arow * 128 + ((aku ^ (arow & 7)) << 4);
            ldm4(fah, sb + OQH + aoff);
            ldm4(fal, sb + OQL + aoff);
            #pragma unroll
            for (int t5 = 0; t5 < 5; t5++) {
                int brow = nbase + t5 * 64 + (l & 7);
                int bku  = 2 * ks + ((l >> 3) & 1);
                uint32_t boff = brow * 128 + ((bku ^ (brow & 7)) << 4);
                uint32_t fb[4], fbl2[4];
                ldm4(fb,   bhi + boff);
                ldm4(fbl2, blo + boff);
                mma_bf16(c[t5],  fah, fb);
                mma_bf16(c[t5],  fah, fbl2);
                mma_bf16(c[t5],  fal, fb);
                mma_bf16(dd[t5], fah, fb + 2);
                mma_bf16(dd[t5], fah, fbl2 + 2);
                mma_bf16(dd[t5], fal, fb + 2);
            }
        }
        #pragma unroll
        for (int t5 = 0; t5 < 5; t5++) {
            int col = nbase + t5 * 64 + (l & 3) * 2;
            int row = m0w + (l >> 2);
            *(float2*)&Ps[row * PSW + col]       = make_float2(c[t5][0], c[t5][1]);
            *(float2*)&Ps[(row + 8) * PSW + col] = make_float2(c[t5][2], c[t5][3]);
        }
        __syncthreads();
        const int sh = S0 - 256;
        #pragma unroll
        for (int t5 = 0; t5 < 5; t5++)
            #pragma unroll
            for (int reg = 0; reg < 4; reg++) {
                int qi  = m0w + (l >> 2) + ((reg >> 1) << 3);
                int rel = nbase + t5 * 64 + ((l & 3) << 1) + (reg & 1);
                int jj  = qi + rel + sh;
                if (jj >= 0 && jj < nk)
                    Ps[qi * PSW + jj] += dd[t5][reg];
            }
    }
    __syncthreads();

    // load PQ over PK region
    for (int idx = tid; idx < KT2 * 8; idx += AT_THREADS) {
        int r = idx >> 3, ku = idx & 7;
        uint32_t off = r * 128 + ((ku ^ (r & 7)) << 4);
        size_t s = pbase + (size_t)r * 64 + ku * 8;
        cpa16(sb + OPOSH + off, ptqh + s);
        cpa16(sb + OPOSL + off, ptql + s);
    }
    CP_COMMIT;
    CP_WAIT0;
    __syncthreads();

    // phase C (bf16 3-product)
    for (int g = warp; g < 20; g += 16) {
        if (16 * g >= nk) continue;
        const int cb = S0 - 16 * g - 15;
        float c[6][4];
        #pragma unroll
        for (int nt = 0; nt < 6; nt++)
            #pragma unroll
            for (int u = 0; u < 4; u++) c[nt][u] = 0.f;
        #pragma unroll
        for (int kc = 0; kc < 4; kc++) {
            uint32_t fah[4], fal[4];
            int arow = 16 * g + (l & 7) + ((l >> 3) & 1) * 8;
            int aku  = 2 * kc + (l >> 4);
            uint32_t aoff = arow * 128 + ((aku ^ (arow & 7)) << 4);
            ldm4(fah, sb + OKH + aoff);
            ldm4(fal, sb + OKL + aoff);
            #pragma unroll
            for (int nt3 = 0; nt3 < 3; nt3++) {
                int brel = cb + nt3 * 16 + (l & 7) + ((l >> 4) & 1) * 8;
                int brow = min(max(brel, 0), KT2 - 1);
                int bku  = 2 * kc + ((l >> 3) & 1);
                uint32_t boff = brow * 128 + ((bku ^ (brow & 7)) << 4);
                uint32_t fbh[4], fbl[4];
                ldm4(fbh, sb + OPOSH + boff);
                ldm4(fbl, sb + OPOSL + boff);
                #pragma unroll
                for (int hh = 0; hh < 2; hh++) {
                    mma_bf16(c[nt3 * 2 + hh], fah, fbh + hh * 2);
                    mma_bf16(c[nt3 * 2 + hh], fah, fbl + hh * 2);
                    mma_bf16(c[nt3 * 2 + hh], fal, fbh + hh * 2);
                }
            }
        }
        #pragma unroll
        for (int nt = 0; nt < 6; nt++)
            #pragma unroll
            for (int reg = 0; reg < 4; reg++) {
                int jj  = 16 * g + (l >> 2) + ((reg >> 1) << 3);
                int rel = cb + nt * 8 + ((l & 3) << 1) + (reg & 1);
                int qi  = rel + jj - S0;
                if (rel >= 0 && qi >= 0 && qi < 32 && jj < nk)
                    Ps[qi * PSW + jj] += c[nt][reg];
            }
    }
    __syncthreads();

    // load V (single fp16, 288 rows max) over POS region; zero pads to 288
    for (int idx = tid; idx < nk * 8; idx += AT_THREADS) {
        int r = idx >> 3, ku = idx & 7;
        uint32_t off = r * 128 + ((ku ^ (r & 7)) << 4);
        size_t s = gbase + (size_t)(jlo + r) * 64 + ku * 8;
        cpa16(sb + OPOSH + off, vf + s);
    }
    CP_COMMIT;
    {
        uint4 z = {0, 0, 0, 0};
        for (int idx = tid; idx < (KTV - nk) * 8; idx += AT_THREADS) {
            int r = nk + (idx >> 3), ku = idx & 7;
            uint32_t off = r * 128 + ((ku ^ (r & 7)) << 4);
            *(uint4*)(sm + OPOSH + off) = z;
        }
    }

    // softmax
    const int qi = tid >> 4, lane16 = tid & 15;
    const int i = i0 + qi;
    float sreg[20];
    {
        float lmax = -INFINITY;
        #pragma unroll
        for (int t = 0; t < 20; t++) {
            int jj = lane16 + (t << 4);
            int rel = (jlo + jj) - i + W_;
            float s = -INFINITY;
            if (jj < nk && rel >= 0 && rel <= 2 * W_)
                s = Ps[qi * PSW + jj];
            sreg[t] = s;
            lmax = fmaxf(lmax, s);
        }
        #pragma unroll
        for (int off = 8; off; off >>= 1)
            lmax = fmaxf(lmax, __shfl_xor_sync(0xffffffffu, lmax, off));
        float lsum = 0.f;
        #pragma unroll
        for (int t = 0; t < 20; t++) {
            float e = __expf(sreg[t] - lmax);
            sreg[t] = e;
            lsum += e;
        }
        #pragma unroll
        for (int off = 8; off; off >>= 1)
            lsum += __shfl_xor_sync(0xffffffffu, lsum, off);
        const float rinv = 1.f / lsum;
        #pragma unroll
        for (int t = 0; t < 20; t++) sreg[t] *= rinv;
    }
    __syncthreads();

    // probs as fp16 hi/lo
    #pragma unroll
    for (int t = 0; t < 20; t++) {
        int jj = lane16 + (t << 4);
        float p = sreg[t];
        __half ph = __float2half_rn(p);
        __half pl = __float2half_rn(p - __half2float(ph));
        int ku = jj >> 3;
        uint32_t boff = qi * 640 + ((((ku & 7) ^ (qi & 7)) | (ku & ~7)) << 4) + ((jj & 7) << 1);
        *(__half*)(sm + OPH2 + boff) = ph;
        *(__half*)(sm + OPL2 + boff) = pl;
    }
    CP_WAIT0;
    __syncthreads();

    // final: warps 0-7 ctx MMA (f16 2-product, 18 K-slices = 288 rows), warps 8-15 proba
    if (warp < 8) {
        const int n0w = warp << 3;
        float c[2][4];
        #pragma unroll
        for (int mh = 0; mh < 2; mh++)
            #pragma unroll
            for (int u = 0; u < 4; u++) c[mh][u] = 0.f;
        #pragma unroll
        for (int ks = 0; ks < 18; ks++) {
            uint32_t fvh[2];
            {
                int jr  = ks * 16 + (l & 15);
                int kuv = warp;
                uint32_t off = jr * 128 + ((kuv ^ (jr & 7)) << 4);
                ldm2t(fvh, sb + OPOSH + off);
            }
            #pragma unroll
            for (int mh = 0; mh < 2; mh++) {
                uint32_t fah[4], fal[4];
                int row = (mh << 4) + (l & 7) + ((l >> 3) & 1) * 8;
                int ku  = 2 * ks + (l >> 4);
                uint32_t off = row * 640 + ((((ku & 7) ^ (row & 7)) | (ku & ~7)) << 4);
                ldm4(fah, sb + OPH2 + off);
                ldm4(fal, sb + OPL2 + off);
                mma_f16(c[mh], fah, fvh);
                mma_f16(c[mh], fal, fvh);
            }
        }
        int b = bh / H_, hd = bh - b * H_;
        #pragma unroll
        for (int mh = 0; mh < 2; mh++) {
            int d  = n0w + (l & 3) * 2;
            int r0 = i0 + (mh << 4) + (l >> 2);
            size_t p0 = ((size_t)(b * N_ + r0)) * HID_ + hd * 64 + d;
            #pragma unroll
            for (int cp = 0; cp < 2; cp++) {
                size_t pp = p0 + (size_t)cp * 8 * HID_;
                float v0 = c[mh][cp * 2 + 0], v1 = c[mh][cp * 2 + 1];
                __half h0 = __float2half_rn(v0), h1 = __float2half_rn(v1);
                __half l0 = __float2half_rn(v0 - __half2float(h0));
                __half l1 = __float2half_rn(v1 - __half2float(h1));
                *(__half2*)(cth + pp) = __halves2half2(h0, h1);
                *(__half2*)(ctl + pp) = __halves2half2(l0, l1);
            }
        }
    } else if (proba) {
        const int w4 = warp - 8;
        const int nf4 = nk >> 2;
        for (int qq = w4 * 4; qq < w4 * 4 + 4; qq++) {
            int ii = i0 + qq;
            float* prow = proba + ((size_t)bh * N_ + ii) * N_ + jlo;
            for (int f4 = l; f4 < nf4; f4 += 32) {
                int j4 = f4 << 2;
                float4 v;
                #pragma unroll
                for (int u = 0; u < 4; u++) {
                    int jj = j4 + u;
                    int ku = jj >> 3;
                    uint32_t boff = qq * 640 + ((((ku & 7) ^ (qq & 7)) | (ku & ~7)) << 4) + ((jj & 7) << 1);
                    ((float*)&v)[u] = __half2float(*(__half*)(sm + OPH2 + boff)) +
                                      __half2float(*(__half*)(sm + OPL2 + boff));
                }
                *(float4*)(prow + j4) = v;
            }
        }
    }
}

// ================================ launch ================================
extern "C" void kernel_launch(void* const* d_in, const int* in_sizes, int n_in,
                              void* d_out, int out_size) {
    const float* hs = (const float*)d_in[0];
    const float* Wq = (const float*)d_in[2];
    const float* Wk = (const float*)d_in[3];
    const float* Wv = (const float*)d_in[4];
    const float* pq = (const float*)d_in[5];
    const float* pk = (const float*)d_in[6];
    const float* Wo = (const float*)d_in[7];
    const float* bo = (const float*)d_in[8];

    const long long OUT_E   = (long long)M_ * HID_;
    const long long PROBA_E = (long long)BH_ * N_ * N_;
    float* out_ptr = nullptr; float* proba_ptr = nullptr;
    if ((long long)out_size == OUT_E + PROBA_E) {
        out_ptr = (float*)d_out; proba_ptr = (float*)d_out + OUT_E;
    } else if ((long long)out_size == PROBA_E) {
        proba_ptr = (float*)d_out;
    } else {
        out_ptr = (float*)d_out;
    }

    bf16 *pQh, *pQl, *pKh, *pKl, *pHh, *pHl;
    bf16 *pWqh, *pWql, *pWkh, *pWkl, *pWvh, *pWvl;
    bf16 *pPQh, *pPQl, *pPKh, *pPKl;
    __half *pVf, *pWof, *pCh, *pCl;
    cudaGetSymbolAddress((void**)&pQh, g_qh);   cudaGetSymbolAddress((void**)&pQl, g_ql);
    cudaGetSymbolAddress((void**)&pKh, g_kh);   cudaGetSymbolAddress((void**)&pKl, g_kl);
    cudaGetSymbolAddress((void**)&pVf, g_vf);
    cudaGetSymbolAddress((void**)&pHh, g_hsh);  cudaGetSymbolAddress((void**)&pHl, g_hsl);
    cudaGetSymbolAddress((void**)&pCh, g_cthf); cudaGetSymbolAddress((void**)&pCl, g_ctlf);
    cudaGetSymbolAddress((void**)&pWqh, g_wqh); cudaGetSymbolAddress((void**)&pWql, g_wql);
    cudaGetSymbolAddress((void**)&pWkh, g_wkh); cudaGetSymbolAddress((void**)&pWkl, g_wkl);
    cudaGetSymbolAddress((void**)&pWvh, g_wvh); cudaGetSymbolAddress((void**)&pWvl, g_wvl);
    cudaGetSymbolAddress((void**)&pWof, g_wof);
    cudaGetSymbolAddress((void**)&pPQh, g_ptqh); cudaGetSymbolAddress((void**)&pPQl, g_ptql);
    cudaGetSymbolAddress((void**)&pPKh, g_ptkh); cudaGetSymbolAddress((void**)&pPKl, g_ptkl);

    // 0: fused prep
    prep<<<(PREP_TOT + 255) / 256, 256>>>(hs, Wq, Wk, Wv, Wo, pq, pk);

    cudaFuncSetAttribute(gemm_mma<3>, cudaFuncAttributeMaxDynamicSharedMemorySize, 98304);
    cudaFuncSetAttribute(gemm_mma<2>, cudaFuncAttributeMaxDynamicSharedMemorySize, 98304);

    // 1: fused QKV projection (+ burst proba zero-fill); V written as fp16 single
    dim3 gQKV(36, M_ / 128);
    gemm_mma<3><<<gQKV, 256, 98304>>>(pHh, pHl, HID_, pWqh, pWql, HID_, HID_, HID_,
                                      2, nullptr, nullptr, 0, pQh, pQl,
                                      pWkh, pWkl, pWvh, pWvl, pKh, pKl,
                                      (bf16*)pVf, nullptr,
                                      proba_ptr, PROBA_E);

    // 2: fully fused band attention
    cudaFuncSetAttribute(attn_fused, cudaFuncAttributeMaxDynamicSharedMemorySize, SMEM_ATTN3);
    attn_fused<<<BH_ * (N_ / 32), AT_THREADS, SMEM_ATTN3>>>(pQh, pQl, pKh, pKl, pVf,
                                                            pPKh, pPKl, pPQh, pPQl,
                                                            proba_ptr, pCh, pCl);

    // 3: output projection (f16 2-product)
    if (out_ptr) {
        dim3 gO(HID_ / 64, M_ / 128);
        gemm_mma<2><<<gO, 256, 98304>>>((bf16*)pCh, (bf16*)pCl, HID_,
                                        (bf16*)pWof, nullptr, HID_, HID_, HID_,
                                        0, bo, out_ptr, HID_, nullptr, nullptr,
                                        nullptr, nullptr, nullptr, nullptr,
                                        nullptr, nullptr, nullptr, nullptr,
                                        nullptr, 0);
    }
}

// round 17
// speedup vs baseline: 1.0109x; 1.0052x over previous
#include <cuda_runtime.h>
#include <cuda_bf16.h>
#include <cuda_fp16.h>
#include <math.h>
#include <stdint.h>

#define B_   2
#define N_   2048
#define HID_ 768
#define H_   12
#define D_   64
#define W_   128
#define P_   257
#define PPAD 320
#define BH_  (B_*H_)      // 24
#define M_   (B_*N_)      // 4096

typedef __nv_bfloat16 bf16;

// ---------------- scratch ----------------
__device__ bf16  g_qh [BH_*N_*D_], g_ql [BH_*N_*D_];
__device__ bf16  g_kh [BH_*N_*D_], g_kl [BH_*N_*D_];
__device__ __half g_vf [BH_*N_*D_];          // V as single fp16
__device__ bf16  g_hsh[M_*HID_],   g_hsl[M_*HID_];
__device__ bf16  g_wqh[HID_*HID_], g_wql[HID_*HID_];
__device__ bf16  g_wkh[HID_*HID_], g_wkl[HID_*HID_];
__device__ bf16  g_wvh[HID_*HID_], g_wvl[HID_*HID_];
__device__ __half g_wof[HID_*HID_];          // Wo as single fp16
__device__ __half g_cthf[M_*HID_], g_ctlf[M_*HID_];   // ctx fp16 hi/lo
__device__ bf16  g_ptqh[H_*PPAD*D_], g_ptql[H_*PPAD*D_];
__device__ bf16  g_ptkh[H_*PPAD*D_], g_ptkl[H_*PPAD*D_];

// ---------------- helpers ----------------
__device__ __forceinline__ void mma_bf16(float* c, const uint32_t* a, const uint32_t* b) {
    asm volatile(
        "mma.sync.aligned.m16n8k16.row.col.f32.bf16.bf16.f32 "
        "{%0,%1,%2,%3},{%4,%5,%6,%7},{%8,%9},{%0,%1,%2,%3};\n"
        : "+f"(c[0]), "+f"(c[1]), "+f"(c[2]), "+f"(c[3])
        : "r"(a[0]), "r"(a[1]), "r"(a[2]), "r"(a[3]), "r"(b[0]), "r"(b[1]));
}
__device__ __forceinline__ void mma_f16(float* c, const uint32_t* a, const uint32_t* b) {
    asm volatile(
        "mma.sync.aligned.m16n8k16.row.col.f32.f16.f16.f32 "
        "{%0,%1,%2,%3},{%4,%5,%6,%7},{%8,%9},{%0,%1,%2,%3};\n"
        : "+f"(c[0]), "+f"(c[1]), "+f"(c[2]), "+f"(c[3])
        : "r"(a[0]), "r"(a[1]), "r"(a[2]), "r"(a[3]), "r"(b[0]), "r"(b[1]));
}
__device__ __forceinline__ void ldm4(uint32_t* r, uint32_t a) {
    asm volatile("ldmatrix.sync.aligned.m8n8.x4.shared.b16 {%0,%1,%2,%3},[%4];\n"
                 : "=r"(r[0]), "=r"(r[1]), "=r"(r[2]), "=r"(r[3]) : "r"(a));
}
__device__ __forceinline__ void ldm2t(uint32_t* r, uint32_t a) {
    asm volatile("ldmatrix.sync.aligned.m8n8.x2.trans.shared.b16 {%0,%1},[%2];\n"
                 : "=r"(r[0]), "=r"(r[1]) : "r"(a));
}
__device__ __forceinline__ void cpa16(uint32_t dst, const void* src) {
    asm volatile("cp.async.cg.shared.global [%0],[%1],16;\n" :: "r"(dst), "l"(src));
}
#define CP_COMMIT asm volatile("cp.async.commit_group;\n" ::: "memory")
#define CP_WAIT0  asm volatile("cp.async.wait_group 0;\n" ::: "memory")

__device__ __forceinline__ void split1(float v, bf16* hi, bf16* lo, size_t i) {
    bf16 h = __float2bfloat16_rn(v);
    hi[i] = h;
    lo[i] = __float2bfloat16_rn(v - __bfloat162float(h));
}

// ---------------- fused prep ----------------
#define SEG0 (M_*HID_)
#define SEGW (HID_*HID_)
#define SEGP (H_*PPAD*D_)
#define PREP_TOT (SEG0 + 4*SEGW + 2*SEGP)

__global__ void prep(const float* __restrict__ hs,
                     const float* __restrict__ Wq, const float* __restrict__ Wk,
                     const float* __restrict__ Wv, const float* __restrict__ Wo,
                     const float* __restrict__ pq, const float* __restrict__ pk)
{
    int i = blockIdx.x * 256 + threadIdx.x;
    if (i < SEG0) { split1(hs[i], g_hsh, g_hsl, i); return; }
    i -= SEG0;
    if (i < 4 * SEGW) {
        int t = i / SEGW, j = i - t * SEGW;
        if (t == 3) { g_wof[j] = __float2half_rn(Wo[j]); return; }
        const float* src = (t == 0) ? Wq : (t == 1) ? Wk : Wv;
        bf16* hi = (t == 0) ? g_wqh : (t == 1) ? g_wkh : g_wvh;
        bf16* lo = (t == 0) ? g_wql : (t == 1) ? g_wkl : g_wvl;
        split1(src[j], hi, lo, j);
        return;
    }
    i -= 4 * SEGW;
    if (i < 2 * SEGP) {
        int t = i / SEGP, j = i - t * SEGP;
        const float* pm = t ? pk : pq;
        bf16* hi = t ? g_ptkh : g_ptqh;
        bf16* lo = t ? g_ptkl : g_ptql;
        int d = j & 63;
        int rest = j >> 6;
        int p = rest % PPAD;
        int h = rest / PPAD;
        float v = (p < P_) ? pm[((size_t)h * D_ + d) * P_ + p] : 0.f;
        split1(v, hi, lo, j);
    }
}

// ---------------- split mma GEMM (128x64, 256 thr, occ2), PROD=3(bf16)/2(f16) ----------------
template<int PROD>
__global__ void __launch_bounds__(256, 2)
gemm_mma(const bf16* __restrict__ Ah, const bf16* __restrict__ Al, int lda,
         const bf16* Bh, const bf16* Bl, int ldb,
         int K, int nvalid, int mode,
         const float* __restrict__ bias,
         float* __restrict__ out, int ldo,
         bf16* sph, bf16* spl,
         const bf16* Bh1, const bf16* Bl1, const bf16* Bh2, const bf16* Bl2,
         bf16* sph1, bf16* spl1, bf16* sph2, bf16* spl2,
         float* pz, long long pztot)
{
    extern __shared__ char smraw[];
    uint32_t s_base = (uint32_t)__cvta_generic_to_shared(smraw);
    const int tid = threadIdx.x, warp = tid >> 5, l = tid & 31;
    const int m0 = blockIdx.y * 128;
    int n0;
    if (mode == 2) {
        int sel = blockIdx.x / 12;
        n0 = (blockIdx.x - sel * 12) * 64;
        if (sel == 1) { Bh = Bh1; Bl = Bl1; sph = sph1; spl = spl1; }
        else if (sel == 2) { Bh = Bh2; Bl = Bl2; sph = sph2; spl = spl2; }
    } else {
        n0 = blockIdx.x * 64;
    }

    auto load_stage = [&](int buf, int k0) {
        uint32_t sA  = s_base + buf * 49152;
        uint32_t sAl = sA + 16384;
        uint32_t sB  = sA + 32768;
        uint32_t sBl = sA + 40960;
        #pragma unroll
        for (int c = 0; c < 4; c++) {
            int idx = tid + c * 256;
            int m = idx >> 3, ku = idx & 7;
            uint32_t off = m * 128 + ((ku ^ (m & 7)) << 4);
            size_t src = (size_t)(m0 + m) * lda + k0 + ku * 8;
            cpa16(sA  + off, Ah + src);
            cpa16(sAl + off, Al + src);
        }
        #pragma unroll
        for (int c = 0; c < 2; c++) {
            int idx = tid + c * 256;
            int n = idx >> 3, ku = idx & 7;
            uint32_t off = n * 128 + ((ku ^ (n & 7)) << 4);
            size_t src = (size_t)(n0 + n) * ldb + k0 + ku * 8;
            cpa16(sB  + off, Bh + src);
            if (PROD == 3) cpa16(sBl + off, Bl + src);
        }
    };

    float acc[2][4][4];
    #pragma unroll
    for (int i = 0; i < 2; i++)
        #pragma unroll
        for (int nt = 0; nt < 4; nt++)
            #pragma unroll
            for (int u = 0; u < 4; u++) acc[i][nt][u] = 0.f;

    const int nst = K >> 6;
    load_stage(0, 0);
    CP_COMMIT;

    if (pz) {
        const long long chunk = 87384;
        long long base = (long long)(blockIdx.y * gridDim.x + blockIdx.x) * chunk;
        long long end = base + chunk;
        if (end > pztot) end = pztot;
        float4 z4 = make_float4(0.f, 0.f, 0.f, 0.f);
        for (long long o = base + (long long)tid * 4; o < end; o += 1024)
            *(float4*)(pz + o) = z4;
    }

    const int wm = (warp >> 1) * 32, wn = (warp & 1) * 32;

    for (int ks = 0; ks < nst; ks++) {
        CP_WAIT0;
        __syncthreads();
        if (ks + 1 < nst) {
            load_stage((ks + 1) & 1, (ks + 1) << 6);
            CP_COMMIT;
        }

        uint32_t sA  = s_base + (ks & 1) * 49152;
        uint32_t sAl = sA + 16384;
        uint32_t sB  = sA + 32768;
        uint32_t sBl = sA + 40960;

        #pragma unroll
        for (int t = 0; t < 4; t++) {
            uint32_t fah[2][4], fal[2][4], fbh[8], fbl[8];
            #pragma unroll
            for (int i = 0; i < 2; i++) {
                int row = wm + 16 * i + (l & 7) + ((l >> 3) & 1) * 8;
                int ku  = 2 * t + (l >> 4);
                uint32_t off = row * 128 + ((ku ^ (row & 7)) << 4);
                ldm4(fah[i], sA  + off);
                ldm4(fal[i], sAl + off);
            }
            #pragma unroll
            for (int hh = 0; hh < 2; hh++) {
                int row = wn + 16 * hh + (l & 7) + ((l >> 4) & 1) * 8;
                int ku  = 2 * t + ((l >> 3) & 1);
                uint32_t off = row * 128 + ((ku ^ (row & 7)) << 4);
                ldm4(&fbh[hh * 4], sB  + off);
                if (PROD == 3) ldm4(&fbl[hh * 4], sBl + off);
            }
            #pragma unroll
            for (int i = 0; i < 2; i++)
                #pragma unroll
                for (int nt = 0; nt < 4; nt++) {
                    const uint32_t* bh2 = &fbh[(nt >> 1) * 4 + (nt & 1) * 2];
                    if (PROD == 3) {
                        const uint32_t* bl2 = &fbl[(nt >> 1) * 4 + (nt & 1) * 2];
                        mma_bf16(acc[i][nt], fah[i], bh2);
                        mma_bf16(acc[i][nt], fah[i], bl2);
                        mma_bf16(acc[i][nt], fal[i], bh2);
                    } else {
                        mma_f16(acc[i][nt], fah[i], bh2);
                        mma_f16(acc[i][nt], fal[i], bh2);
                    }
                }
        }
    }

    #pragma unroll
    for (int i = 0; i < 2; i++)
        #pragma unroll
        for (int nt = 0; nt < 4; nt++)
            #pragma unroll
            for (int cp = 0; cp < 2; cp++) {
                int r   = m0 + wm + 16 * i + (l >> 2) + cp * 8;
                int gn0 = n0 + wn + nt * 8 + (l & 3) * 2;
                float v0 = acc[i][nt][cp * 2 + 0];
                float v1 = acc[i][nt][cp * 2 + 1];
                if (mode == 0) {
                    if (gn0 < nvalid) {
                        float b0 = bias ? bias[gn0] : 0.f;
                        out[(size_t)r * ldo + gn0] = v0 + b0;
                    }
                    if (gn0 + 1 < nvalid) {
                        float b1 = bias ? bias[gn0 + 1] : 0.f;
                        out[(size_t)r * ldo + gn0 + 1] = v1 + b1;
                    }
                } else {
                    int b = r >> 11, nn = r & 2047;
                    #pragma unroll
                    for (int u = 0; u < 2; u++) {
                        int gn = gn0 + u;
                        float v = u ? v1 : v0;
                        int h = gn >> 6, d = gn & 63;
                        size_t idx = (((size_t)(b * H_ + h) * N_ + nn) << 6) + d;
                        if (spl == nullptr) {
                            ((__half*)sph)[idx] = __float2half_rn(v);   // V fp16 single
                        } else {
                            bf16 hv = __float2bfloat16_rn(v);
                            sph[idx] = hv;
                            spl[idx] = __float2bfloat16_rn(v - __bfloat162float(hv));
                        }
                    }
                }
            }
}

// ============== fully fused band attention (512 threads) ==============
#define OQH   0
#define OQL   4096
#define OKH   8192
#define OKL   49152
#define OPOSH 90112
#define OPOSL 131072
#define OPS   172032
#define OPH2  OPS
#define OPL2  (OPS + 20480)
#define SMEM_ATTN3 214016
#define KT2 320
#define KTV 288
#define PSW 328
#define AT_THREADS 512

__global__ void __launch_bounds__(AT_THREADS, 1)
attn_fused(const bf16* __restrict__ qh, const bf16* __restrict__ ql,
           const bf16* __restrict__ kh, const bf16* __restrict__ kl,
           const __half* __restrict__ vf,
           const bf16* __restrict__ ptkh, const bf16* __restrict__ ptkl,
           const bf16* __restrict__ ptqh, const bf16* __restrict__ ptql,
           float* __restrict__ proba, __half* __restrict__ cth, __half* __restrict__ ctl)
{
    const int bid = blockIdx.x;
    const int bh = bid >> 6, tile = bid & 63;
    const int h = bh % H_;
    const int i0 = tile * 32;
    const int jlo = max(0, i0 - W_);
    const int jhi = min(N_, i0 + 32 + W_);
    const int nk = jhi - jlo;          // <= 288
    const int S0 = i0 - jlo + W_;

    extern __shared__ char sm[];
    const uint32_t sb = (uint32_t)__cvta_generic_to_shared(sm);
    const int tid = threadIdx.x, warp = tid >> 5, l = tid & 31;
    const size_t gbase = (size_t)bh * N_ * D_;
    const size_t pbase = (size_t)h * PPAD * D_;
    float* Ps = (float*)(sm + OPS);

    {
        int idx = tid;
        int m = idx & 255;
        int r = m >> 3, ku = m & 7;
        uint32_t off = r * 128 + ((ku ^ (r & 7)) << 4);
        size_t s = gbase + (size_t)(i0 + r) * 64 + ku * 8;
        if (idx < 256) cpa16(sb + OQH + off, qh + s);
        else           cpa16(sb + OQL + off, ql + s);
    }
    for (int idx = tid; idx < nk * 8; idx += AT_THREADS) {
        int r = idx >> 3, ku = idx & 7;
        uint32_t off = r * 128 + ((ku ^ (r & 7)) << 4);
        size_t s = gbase + (size_t)(jlo + r) * 64 + ku * 8;
        cpa16(sb + OKH + off, kh + s);
        cpa16(sb + OKL + off, kl + s);
    }
    for (int idx = tid; idx < KT2 * 8; idx += AT_THREADS) {
        int r = idx >> 3, ku = idx & 7;
        uint32_t off = r * 128 + ((ku ^ (r & 7)) << 4);
        size_t s = pbase + (size_t)r * 64 + ku * 8;
        cpa16(sb + OPOSH + off, ptkh + s);
        cpa16(sb + OPOSL + off, ptkl + s);
    }
    CP_COMMIT;
    CP_WAIT0;
    __syncthreads();

    // fused phases A+B (bf16 3-product); K+PK fragments fused into single ldm4
    {
        const int mh    = warp >> 3;
        const int m0w   = mh << 4;
        const int nbase = (warp & 7) << 3;
        float c[5][4], dd[5][4];
        #pragma unroll
        for (int t5 = 0; t5 < 5; t5++)
            #pragma unroll
            for (int u = 0; u < 4; u++) { c[t5][u] = 0.f; dd[t5][u] = 0.f; }

        const uint32_t bhi = (l < 16) ? (sb + OKH) : (sb + OPOSH);
        const uint32_t blo = (l < 16) ? (sb + OKL) : (sb + OPOSL);

        #pragma unroll
        for (int ks = 0; ks < 4; ks++) {
            uint32_t fah[4], fal[4];
            int arow = m0w + (l & 7) + ((l >> 3) & 1) * 8;
            int aku  = 2 * ks + (l >> 4);
            uint32_t aoff = arow * 128 + ((aku ^ (arow & 7)) << 4);
            ldm4(fah, sb + OQH + aoff);
            ldm4(fal, sb + OQL + aoff);
            #pragma unroll
            for (int t5 = 0; t5 < 5; t5++) {
                int brow = nbase + t5 * 64 + (l & 7);
                int bku  = 2 * ks + ((l >> 3) & 1);
                uint32_t boff = brow * 128 + ((bku ^ (brow & 7)) << 4);
                uint32_t fb[4], fbl2[4];
                ldm4(fb,   bhi + boff);
                ldm4(fbl2, blo + boff);
                mma_bf16(c[t5],  fah, fb);
                mma_bf16(c[t5],  fah, fbl2);
                mma_bf16(c[t5],  fal, fb);
                mma_bf16(dd[t5], fah, fb + 2);
                mma_bf16(dd[t5], fah, fbl2 + 2);
                mma_bf16(dd[t5], fal, fb + 2);
            }
        }
        #pragma unroll
        for (int t5 = 0; t5 < 5; t5++) {
            int col = nbase + t5 * 64 + (l & 3) * 2;
            int row = m0w + (l >> 2);
            *(float2*)&Ps[row * PSW + col]       = make_float2(c[t5][0], c[t5][1]);
            *(float2*)&Ps[(row + 8) * PSW + col] = make_float2(c[t5][2], c[t5][3]);
        }
        __syncthreads();   // all PK ldmatrix reads done -> POS region dead

        // overlap: issue PQ loads over the dead POS region, scatter while they fly
        for (int idx = tid; idx < KT2 * 8; idx += AT_THREADS) {
            int r = idx >> 3, ku = idx & 7;
            uint32_t off = r * 128 + ((ku ^ (r & 7)) << 4);
            size_t s = pbase + (size_t)r * 64 + ku * 8;
            cpa16(sb + OPOSH + off, ptqh + s);
            cpa16(sb + OPOSL + off, ptql + s);
        }
        CP_COMMIT;

        const int sh = S0 - 256;
        #pragma unroll
        for (int t5 = 0; t5 < 5; t5++)
            #pragma unroll
            for (int reg = 0; reg < 4; reg++) {
                int qi  = m0w + (l >> 2) + ((reg >> 1) << 3);
                int rel = nbase + t5 * 64 + ((l & 3) << 1) + (reg & 1);
                int jj  = qi + rel + sh;
                if (jj >= 0 && jj < nk)
                    Ps[qi * PSW + jj] += dd[t5][reg];
            }
    }
    CP_WAIT0;
    __syncthreads();

    // phase C (bf16 3-product)
    for (int g = warp; g < 20; g += 16) {
        if (16 * g >= nk) continue;
        const int cb = S0 - 16 * g - 15;
        float c[6][4];
        #pragma unroll
        for (int nt = 0; nt < 6; nt++)
            #pragma unroll
            for (int u = 0; u < 4; u++) c[nt][u] = 0.f;
        #pragma unroll
        for (int kc = 0; kc < 4; kc++) {
            uint32_t fah[4], fal[4];
            int arow = 16 * g + (l & 7) + ((l >> 3) & 1) * 8;
            int aku  = 2 * kc + (l >> 4);
            uint32_t aoff = arow * 128 + ((aku ^ (arow & 7)) << 4);
            ldm4(fah, sb + OKH + aoff);
            ldm4(fal, sb + OKL + aoff);
            #pragma unroll
            for (int nt3 = 0; nt3 < 3; nt3++) {
                int brel = cb + nt3 * 16 + (l & 7) + ((l >> 4) & 1) * 8;
                int brow = min(max(brel, 0), KT2 - 1);
                int bku  = 2 * kc + ((l >> 3) & 1);
                uint32_t boff = brow * 128 + ((bku ^ (brow & 7)) << 4);
                uint32_t fbh[4], fbl[4];
                ldm4(fbh, sb + OPOSH + boff);
                ldm4(fbl, sb + OPOSL + boff);
                #pragma unroll
                for (int hh = 0; hh < 2; hh++) {
                    mma_bf16(c[nt3 * 2 + hh], fah, fbh + hh * 2);
                    mma_bf16(c[nt3 * 2 + hh], fah, fbl + hh * 2);
                    mma_bf16(c[nt3 * 2 + hh], fal, fbh + hh * 2);
                }
            }
        }
        #pragma unroll
        for (int nt = 0; nt < 6; nt++)
            #pragma unroll
            for (int reg = 0; reg < 4; reg++) {
                int jj  = 16 * g + (l >> 2) + ((reg >> 1) << 3);
                int rel = cb + nt * 8 + ((l & 3) << 1) + (reg & 1);
                int qi  = rel + jj - S0;
                if (rel >= 0 && qi >= 0 && qi < 32 && jj < nk)
                    Ps[qi * PSW + jj] += c[nt][reg];
            }
    }
    __syncthreads();

    // load V (single fp16, 288 rows max) over POS region; zero pads to 288
    for (int idx = tid; idx < nk * 8; idx += AT_THREADS) {
        int r = idx >> 3, ku = idx & 7;
        uint32_t off = r * 128 + ((ku ^ (r & 7)) << 4);
        size_t s = gbase + (size_t)(jlo + r) * 64 + ku * 8;
        cpa16(sb + OPOSH + off, vf + s);
    }
    CP_COMMIT;
    {
        uint4 z = {0, 0, 0, 0};
        for (int idx = tid; idx < (KTV - nk) * 8; idx += AT_THREADS) {
            int r = nk + (idx >> 3), ku = idx & 7;
            uint32_t off = r * 128 + ((ku ^ (r & 7)) << 4);
            *(uint4*)(sm + OPOSH + off) = z;
        }
    }

    // softmax
    const int qi = tid >> 4, lane16 = tid & 15;
    const int i = i0 + qi;
    float sreg[20];
    {
        float lmax = -INFINITY;
        #pragma unroll
        for (int t = 0; t < 20; t++) {
            int jj = lane16 + (t << 4);
            int rel = (jlo + jj) - i + W_;
            float s = -INFINITY;
            if (jj < nk && rel >= 0 && rel <= 2 * W_)
                s = Ps[qi * PSW + jj];
            sreg[t] = s;
            lmax = fmaxf(lmax, s);
        }
        #pragma unroll
        for (int off = 8; off; off >>= 1)
            lmax = fmaxf(lmax, __shfl_xor_sync(0xffffffffu, lmax, off));
        float lsum = 0.f;
        #pragma unroll
        for (int t = 0; t < 20; t++) {
            float e = __expf(sreg[t] - lmax);
            sreg[t] = e;
            lsum += e;
        }
        #pragma unroll
        for (int off = 8; off; off >>= 1)
            lsum += __shfl_xor_sync(0xffffffffu, lsum, off);
        const float rinv = 1.f / lsum;
        #pragma unroll
        for (int t = 0; t < 20; t++) sreg[t] *= rinv;
    }
    __syncthreads();

    // probs as fp16 hi/lo
    #pragma unroll
    for (int t = 0; t < 20; t++) {
        int jj = lane16 + (t << 4);
        float p = sreg[t];
        __half ph = __float2half_rn(p);
        __half pl = __float2half_rn(p - __half2float(ph));
        int ku = jj >> 3;
        uint32_t boff = qi * 640 + ((((ku & 7) ^ (qi & 7)) | (ku & ~7)) << 4) + ((jj & 7) << 1);
        *(__half*)(sm + OPH2 + boff) = ph;
        *(__half*)(sm + OPL2 + boff) = pl;
    }
    CP_WAIT0;
    __syncthreads();

    // final: warps 0-7 ctx MMA (f16 2-product, 18 K-slices), warps 8-15 band-only proba
    if (warp < 8) {
        const int n0w = warp << 3;
        float c[2][4];
        #pragma unroll
        for (int mh = 0; mh < 2; mh++)
            #pragma unroll
            for (int u = 0; u < 4; u++) c[mh][u] = 0.f;
        #pragma unroll
        for (int ks = 0; ks < 18; ks++) {
            uint32_t fvh[2];
            {
                int jr  = ks * 16 + (l & 15);
                int kuv = warp;
                uint32_t off = jr * 128 + ((kuv ^ (jr & 7)) << 4);
                ldm2t(fvh, sb + OPOSH + off);
            }
            #pragma unroll
            for (int mh = 0; mh < 2; mh++) {
                uint32_t fah[4], fal[4];
                int row = (mh << 4) + (l & 7) + ((l >> 3) & 1) * 8;
                int ku  = 2 * ks + (l >> 4);
                uint32_t off = row * 640 + ((((ku & 7) ^ (row & 7)) | (ku & ~7)) << 4);
                ldm4(fah, sb + OPH2 + off);
                ldm4(fal, sb + OPL2 + off);
                mma_f16(c[mh], fah, fvh);
                mma_f16(c[mh], fal, fvh);
            }
        }
        int b = bh / H_, hd = bh - b * H_;
        #pragma unroll
        for (int mh = 0; mh < 2; mh++) {
            int d  = n0w + (l & 3) * 2;
            int r0 = i0 + (mh << 4) + (l >> 2);
            size_t p0 = ((size_t)(b * N_ + r0)) * HID_ + hd * 64 + d;
            #pragma unroll
            for (int cp = 0; cp < 2; cp++) {
                size_t pp = p0 + (size_t)cp * 8 * HID_;
                float v0 = c[mh][cp * 2 + 0], v1 = c[mh][cp * 2 + 1];
                __half h0 = __float2half_rn(v0), h1 = __float2half_rn(v1);
                __half l0 = __float2half_rn(v0 - __half2float(h0));
                __half l1 = __float2half_rn(v1 - __half2float(h1));
                *(__half2*)(cth + pp) = __halves2half2(h0, h1);
                *(__half2*)(ctl + pp) = __halves2half2(l0, l1);
            }
        }
    } else if (proba) {
        const int w4 = warp - 8;
        const int nf4 = nk >> 2;
        for (int qq = w4 * 4; qq < w4 * 4 + 4; qq++) {
            int ii = i0 + qq;
            float* prow = proba + ((size_t)bh * N_ + ii) * N_ + jlo;
            for (int f4 = l; f4 < nf4; f4 += 32) {
                int j4 = f4 << 2;
                float4 v;
                #pragma unroll
                for (int u = 0; u < 4; u++) {
                    int jj = j4 + u;
                    int ku = jj >> 3;
                    uint32_t boff = qq * 640 + ((((ku & 7) ^ (qq & 7)) | (ku & ~7)) << 4) + ((jj & 7) << 1);
                    ((float*)&v)[u] = __half2float(*(__half*)(sm + OPH2 + boff)) +
                                      __half2float(*(__half*)(sm + OPL2 + boff));
                }
                *(float4*)(prow + j4) = v;
            }
        }
    }
}

// ================================ launch ================================
extern "C" void kernel_launch(void* const* d_in, const int* in_sizes, int n_in,
                              void* d_out, int out_size) {
    const float* hs = (const float*)d_in[0];
    const float* Wq = (const float*)d_in[2];
    const float* Wk = (const float*)d_in[3];
    const float* Wv = (const float*)d_in[4];
    const float* pq = (const float*)d_in[5];
    const float* pk = (const float*)d_in[6];
    const float* Wo = (const float*)d_in[7];
    const float* bo = (const float*)d_in[8];

    const long long OUT_E   = (long long)M_ * HID_;
    const long long PROBA_E = (long long)BH_ * N_ * N_;
    float* out_ptr = nullptr; float* proba_ptr = nullptr;
    if ((long long)out_size == OUT_E + PROBA_E) {
        out_ptr = (float*)d_out; proba_ptr = (float*)d_out + OUT_E;
    } else if ((long long)out_size == PROBA_E) {
        proba_ptr = (float*)d_out;
    } else {
        out_ptr = (float*)d_out;
    }

    bf16 *pQh, *pQl, *pKh, *pKl, *pHh, *pHl;
    bf16 *pWqh, *pWql, *pWkh, *pWkl, *pWvh, *pWvl;
    bf16 *pPQh, *pPQl, *pPKh, *pPKl;
    __half *pVf, *pWof, *pCh, *pCl;
    cudaGetSymbolAddress((void**)&pQh, g_qh);   cudaGetSymbolAddress((void**)&pQl, g_ql);
    cudaGetSymbolAddress((void**)&pKh, g_kh);   cudaGetSymbolAddress((void**)&pKl, g_kl);
    cudaGetSymbolAddress((void**)&pVf, g_vf);
    cudaGetSymbolAddress((void**)&pHh, g_hsh);  cudaGetSymbolAddress((void**)&pHl, g_hsl);
    cudaGetSymbolAddress((void**)&pCh, g_cthf); cudaGetSymbolAddress((void**)&pCl, g_ctlf);
    cudaGetSymbolAddress((void**)&pWqh, g_wqh); cudaGetSymbolAddress((void**)&pWql, g_wql);
    cudaGetSymbolAddress((void**)&pWkh, g_wkh); cudaGetSymbolAddress((void**)&pWkl, g_wkl);
    cudaGetSymbolAddress((void**)&pWvh, g_wvh); cudaGetSymbolAddress((void**)&pWvl, g_wvl);
    cudaGetSymbolAddress((void**)&pWof, g_wof);
    cudaGetSymbolAddress((void**)&pPQh, g_ptqh); cudaGetSymbolAddress((void**)&pPQl, g_ptql);
    cudaGetSymbolAddress((void**)&pPKh, g_ptkh); cudaGetSymbolAddress((void**)&pPKl, g_ptkl);

    // 0: fused prep
    prep<<<(PREP_TOT + 255) / 256, 256>>>(hs, Wq, Wk, Wv, Wo, pq, pk);

    cudaFuncSetAttribute(gemm_mma<3>, cudaFuncAttributeMaxDynamicSharedMemorySize, 98304);
    cudaFuncSetAttribute(gemm_mma<2>, cudaFuncAttributeMaxDynamicSharedMemorySize, 98304);

    // 1: fused QKV projection (+ burst proba zero-fill); V written as fp16 single
    dim3 gQKV(36, M_ / 128);
    gemm_mma<3><<<gQKV, 256, 98304>>>(pHh, pHl, HID_, pWqh, pWql, HID_, HID_, HID_,
                                      2, nullptr, nullptr, 0, pQh, pQl,
                                      pWkh, pWkl, pWvh, pWvl, pKh, pKl,
                                      (bf16*)pVf, nullptr,
                                      proba_ptr, PROBA_E);

    // 2: fully fused band attention
    cudaFuncSetAttribute(attn_fused, cudaFuncAttributeMaxDynamicSharedMemorySize, SMEM_ATTN3);
    attn_fused<<<BH_ * (N_ / 32), AT_THREADS, SMEM_ATTN3>>>(pQh, pQl, pKh, pKl, pVf,
                                                            pPKh, pPKl, pPQh, pPQl,
                                                            proba_ptr, pCh, pCl);

    // 3: output projection (f16 2-product)
    if (out_ptr) {
        dim3 gO(HID_ / 64, M_ / 128);
        gemm_mma<2><<<gO, 256, 98304>>>((bf16*)pCh, (bf16*)pCl, HID_,
                                        (bf16*)pWof, nullptr, HID_, HID_, HID_,
                                        0, bo, out_ptr, HID_, nullptr, nullptr,
                                        nullptr, nullptr, nullptr, nullptr,
                                        nullptr, nullptr, nullptr, nullptr,
                                        nullptr, 0);
    }
}